// round 2
// baseline (speedup 1.0000x reference)
#include <cuda_runtime.h>

// ---------------- problem constants ----------------
#define NTHREAD 128
#define RW 4                 // rows per warp
#define ROWS 16              // rows per CTA
static constexpr int Bb = 2048, Tt = 256, Ff = 64;
static constexpr int K0 = 128, N0 = 256;   // layer0: concat [x(64)|h0(64)] -> 4*64
static constexpr int K1 = 96,  N1 = 128;   // layer1: concat [h0(64)|h1(32)] -> 4*32
static constexpr int K2 = 48,  N2 = 64;    // layer2: concat [h1(32)|h2(16)] -> 4*16

// ---------------- shared memory layout (float offsets) ----------------
static constexpr int OFF_W0 = 0;
static constexpr int OFF_W1 = OFF_W0 + K0 * N0;      // 32768
static constexpr int OFF_W2 = OFF_W1 + K1 * N1;      // 45056
static constexpr int OFF_B0 = OFF_W2 + K2 * N2;      // 48128
static constexpr int OFF_B1 = OFF_B0 + N0;           // 48384
static constexpr int OFF_B2 = OFF_B1 + N1;           // 48512
static constexpr int OFF_WD = OFF_B2 + N2;           // 48576
static constexpr int OFF_V0 = OFF_WD + 16;           // 48592 (16B aligned)
static constexpr int OFF_V1 = OFF_V0 + ROWS * K0;    // 50640
static constexpr int OFF_V2 = OFF_V1 + ROWS * K1;    // 52176
static constexpr int SMEM_FLOATS = OFF_V2 + ROWS * K2;  // 52944
static constexpr size_t SMEM_BYTES = (size_t)SMEM_FLOATS * sizeof(float); // 211776 B

// ---------------- packed f32x2 helpers ----------------
__device__ __forceinline__ void fma2(unsigned long long& acc,
                                     unsigned long long a, unsigned long long b) {
    asm("fma.rn.f32x2 %0, %1, %2, %0;" : "+l"(acc) : "l"(a), "l"(b));
}
__device__ __forceinline__ unsigned long long dup2(float v) {
    unsigned long long u;
    asm("mov.b64 %0, {%1, %1};" : "=l"(u) : "f"(v));
    return u;
}
__device__ __forceinline__ float2 unpk(unsigned long long u) {
    float2 r;
    asm("mov.b64 {%0, %1}, %2;" : "=f"(r.x), "=f"(r.y) : "l"(u));
    return r;
}
// overflow-safe fast activations (rel err ~1e-6, far under 1e-3 budget)
__device__ __forceinline__ float sigf(float x) {
    return __fdividef(1.0f, 1.0f + __expf(-x));
}
__device__ __forceinline__ float tanhf_(float x) {
    float e = __expf(-2.0f * x);
    return __fdividef(2.0f, 1.0f + e) - 1.0f;   // = 2*sigmoid(2x)-1; no NaN at |x| large
}

// column permutations so thread reads its (rp) pairs with LDS.128:
// layer0: thread `l` float4 at [k][g*128 + l*4] = pairs (rp=2g, rp=2g+1), j = 2l + 64*rp
__device__ __forceinline__ int perm0(int j) {
    int jp = j >> 1, e = j & 1, rp = jp >> 5, l = jp & 31, g = rp >> 1, s = rp & 1;
    return g * 128 + l * 4 + s * 2 + e;
}
// layer1: thread `l` float4 at [k][l*4] = pairs (rp=0, rp=1), j = 2l + 64*rp
__device__ __forceinline__ int perm1(int j) {
    int jp = j >> 1, e = j & 1, rp = jp >> 5, l = jp & 31;
    return l * 4 + rp * 2 + e;
}

__global__ void __launch_bounds__(NTHREAD, 1)
stacked_lstm_kernel(const float* __restrict__ x,
                    const float* __restrict__ W0, const float* __restrict__ U0, const float* __restrict__ b0,
                    const float* __restrict__ W1, const float* __restrict__ U1, const float* __restrict__ b1,
                    const float* __restrict__ W2, const float* __restrict__ U2, const float* __restrict__ b2,
                    const float* __restrict__ Wd, const float* __restrict__ bd,
                    float* __restrict__ out) {
    extern __shared__ float S[];
    const int tid = threadIdx.x, lane = tid & 31, warp = tid >> 5;

    // ---- stage weights (permuted) into smem ----
    for (int idx = tid; idx < K0 * N0; idx += NTHREAD) {
        int k = idx >> 8, j = idx & (N0 - 1);
        float v = (k < 64) ? W0[k * N0 + j] : U0[(k - 64) * N0 + j];
        S[OFF_W0 + k * N0 + perm0(j)] = v;
    }
    for (int idx = tid; idx < K1 * N1; idx += NTHREAD) {
        int k = idx >> 7, j = idx & (N1 - 1);
        float v = (k < 64) ? W1[k * N1 + j] : U1[(k - 64) * N1 + j];
        S[OFF_W1 + k * N1 + perm1(j)] = v;
    }
    for (int idx = tid; idx < K2 * N2; idx += NTHREAD) {
        int k = idx >> 6, j = idx & (N2 - 1);
        S[OFF_W2 + idx] = (k < 32) ? W2[k * N2 + j] : U2[(k - 32) * N2 + j];
    }
    for (int j = tid; j < N0; j += NTHREAD) S[OFF_B0 + perm0(j)] = b0[j];
    if (tid < N1) S[OFF_B1 + perm1(tid)] = b1[tid];
    if (tid < N2) S[OFF_B2 + tid] = b2[tid];
    if (tid < 16) S[OFF_WD + tid] = Wd[tid];
    for (int i = tid; i < ROWS * (K0 + K1 + K2); i += NTHREAD) S[OFF_V0 + i] = 0.0f;
    __syncthreads();

    // ---- per-warp row ownership ----
    const int rl0 = warp * RW;
    const int grow0 = blockIdx.x * ROWS + rl0;
    float* v0b[RW]; float* v1b[RW]; float* v2b[RW];
    const float* xp[RW];
#pragma unroll
    for (int r = 0; r < RW; r++) {
        v0b[r] = S + OFF_V0 + (rl0 + r) * K0;
        v1b[r] = S + OFF_V1 + (rl0 + r) * K1;
        v2b[r] = S + OFF_V2 + (rl0 + r) * K2;
        xp[r] = x + (size_t)(grow0 + r) * (Tt * Ff) + 2 * lane;
    }
    float c0x[RW], c0y[RW], c1x[RW], c1y[RW], c2x[RW], c2y[RW];
#pragma unroll
    for (int r = 0; r < RW; r++) {
        c0x[r] = c0y[r] = c1x[r] = c1y[r] = c2x[r] = c2y[r] = 0.0f;
    }

    float2 xr[RW];
#pragma unroll
    for (int r = 0; r < RW; r++) xr[r] = *(const float2*)(xp[r]);

    for (int t = 0; t < Tt; t++) {
        // commit x_t to v0[0..63]; prefetch x_{t+1}
#pragma unroll
        for (int r = 0; r < RW; r++) *(float2*)(v0b[r] + 2 * lane) = xr[r];
        if (t + 1 < Tt) {
#pragma unroll
            for (int r = 0; r < RW; r++) xr[r] = *(const float2*)(xp[r] + (t + 1) * Ff);
        }
        __syncwarp();

        // ================= layer 0 (H=64) =================
        unsigned long long a0[RW], a1[RW], a2[RW], a3[RW];
        {
            longlong2 bA = *(const longlong2*)(S + OFF_B0 + lane * 4);
            longlong2 bB = *(const longlong2*)(S + OFF_B0 + 128 + lane * 4);
#pragma unroll
            for (int r = 0; r < RW; r++) { a0[r] = bA.x; a1[r] = bA.y; a2[r] = bB.x; a3[r] = bB.y; }
        }
#pragma unroll 4
        for (int k4 = 0; k4 < K0 / 4; k4++) {
            float4 vv[RW];
#pragma unroll
            for (int r = 0; r < RW; r++) vv[r] = *(const float4*)(v0b[r] + k4 * 4);
#pragma unroll
            for (int kk = 0; kk < 4; kk++) {
                const float* wr = S + OFF_W0 + (k4 * 4 + kk) * N0 + lane * 4;
                longlong2 wA = *(const longlong2*)(wr);
                longlong2 wB = *(const longlong2*)(wr + 128);
#pragma unroll
                for (int r = 0; r < RW; r++) {
                    float vk = (kk == 0) ? vv[r].x : (kk == 1) ? vv[r].y : (kk == 2) ? vv[r].z : vv[r].w;
                    unsigned long long d = dup2(vk);
                    fma2(a0[r], d, wA.x); fma2(a1[r], d, wA.y);
                    fma2(a2[r], d, wB.x); fma2(a3[r], d, wB.y);
                }
            }
        }
#pragma unroll
        for (int r = 0; r < RW; r++) {
            float2 zi = unpk(a0[r]), zf = unpk(a1[r]), zg = unpk(a2[r]), zo = unpk(a3[r]);
            c0x[r] = sigf(zf.x) * c0x[r] + sigf(zi.x) * tanhf_(zg.x);
            c0y[r] = sigf(zf.y) * c0y[r] + sigf(zi.y) * tanhf_(zg.y);
            float2 h;
            h.x = sigf(zo.x) * tanhf_(c0x[r]);
            h.y = sigf(zo.y) * tanhf_(c0y[r]);
            *(float2*)(v0b[r] + 64 + 2 * lane) = h;   // recurrent input next step
            *(float2*)(v1b[r] + 2 * lane) = h;        // layer1 input
        }
        __syncwarp();

        // ================= layer 1 (H=32) =================
        unsigned long long p0[RW], p1[RW];
        {
            longlong2 bb = *(const longlong2*)(S + OFF_B1 + lane * 4);
#pragma unroll
            for (int r = 0; r < RW; r++) { p0[r] = bb.x; p1[r] = bb.y; }
        }
#pragma unroll 4
        for (int k4 = 0; k4 < K1 / 4; k4++) {
            float4 vv[RW];
#pragma unroll
            for (int r = 0; r < RW; r++) vv[r] = *(const float4*)(v1b[r] + k4 * 4);
#pragma unroll
            for (int kk = 0; kk < 4; kk++) {
                longlong2 w = *(const longlong2*)(S + OFF_W1 + (k4 * 4 + kk) * N1 + lane * 4);
#pragma unroll
                for (int r = 0; r < RW; r++) {
                    float vk = (kk == 0) ? vv[r].x : (kk == 1) ? vv[r].y : (kk == 2) ? vv[r].z : vv[r].w;
                    unsigned long long d = dup2(vk);
                    fma2(p0[r], d, w.x); fma2(p1[r], d, w.y);
                }
            }
        }
#pragma unroll
        for (int r = 0; r < RW; r++) {
            float2 zA = unpk(p0[r]), zB = unpk(p1[r]);  // lanes<16: (i,g); lanes>=16: (f,o)
            float fx = __shfl_down_sync(0xffffffffu, zA.x, 16);
            float fy = __shfl_down_sync(0xffffffffu, zA.y, 16);
            float ox = __shfl_down_sync(0xffffffffu, zB.x, 16);
            float oy = __shfl_down_sync(0xffffffffu, zB.y, 16);
            if (lane < 16) {
                c1x[r] = sigf(fx) * c1x[r] + sigf(zA.x) * tanhf_(zB.x);
                c1y[r] = sigf(fy) * c1y[r] + sigf(zA.y) * tanhf_(zB.y);
                float2 h;
                h.x = sigf(ox) * tanhf_(c1x[r]);
                h.y = sigf(oy) * tanhf_(c1y[r]);
                *(float2*)(v1b[r] + 64 + 2 * lane) = h;
                *(float2*)(v2b[r] + 2 * lane) = h;
            }
        }
        __syncwarp();

        // ================= layer 2 (H=16) =================
        unsigned long long q[RW];
        {
            unsigned long long bq = *(const unsigned long long*)(S + OFF_B2 + 2 * lane);
#pragma unroll
            for (int r = 0; r < RW; r++) q[r] = bq;
        }
#pragma unroll 4
        for (int k4 = 0; k4 < K2 / 4; k4++) {
            float4 vv[RW];
#pragma unroll
            for (int r = 0; r < RW; r++) vv[r] = *(const float4*)(v2b[r] + k4 * 4);
#pragma unroll
            for (int kk = 0; kk < 4; kk++) {
                unsigned long long w = *(const unsigned long long*)(S + OFF_W2 + (k4 * 4 + kk) * N2 + 2 * lane);
#pragma unroll
                for (int r = 0; r < RW; r++) {
                    float vk = (kk == 0) ? vv[r].x : (kk == 1) ? vv[r].y : (kk == 2) ? vv[r].z : vv[r].w;
                    fma2(q[r], dup2(vk), w);
                }
            }
        }
#pragma unroll
        for (int r = 0; r < RW; r++) {
            float2 z = unpk(q[r]);  // lanes 0-7: i pair; 8-15: f; 16-23: g; 24-31: o
            float fx = __shfl_down_sync(0xffffffffu, z.x, 8);
            float fy = __shfl_down_sync(0xffffffffu, z.y, 8);
            float gx = __shfl_down_sync(0xffffffffu, z.x, 16);
            float gy = __shfl_down_sync(0xffffffffu, z.y, 16);
            float ox = __shfl_down_sync(0xffffffffu, z.x, 24);
            float oy = __shfl_down_sync(0xffffffffu, z.y, 24);
            if (lane < 8) {
                c2x[r] = sigf(fx) * c2x[r] + sigf(z.x) * tanhf_(gx);
                c2y[r] = sigf(fy) * c2y[r] + sigf(z.y) * tanhf_(gy);
                float2 h;
                h.x = sigf(ox) * tanhf_(c2x[r]);
                h.y = sigf(oy) * tanhf_(c2y[r]);
                *(float2*)(v2b[r] + 32 + 2 * lane) = h;
            }
        }
        __syncwarp();
    }

    // ================= dense head =================
    const float bdv = bd[0];
#pragma unroll
    for (int r = 0; r < RW; r++) {
        float p = (lane < 16) ? v2b[r][32 + lane] * S[OFF_WD + lane] : 0.0f;
#pragma unroll
        for (int off = 8; off > 0; off >>= 1) p += __shfl_down_sync(0xffffffffu, p, off);
        if (lane == 0) out[grow0 + r] = p + bdv;
    }
}

extern "C" void kernel_launch(void* const* d_in, const int* in_sizes, int n_in,
                              void* d_out, int out_size) {
    cudaFuncSetAttribute(stacked_lstm_kernel,
                         cudaFuncAttributeMaxDynamicSharedMemorySize, (int)SMEM_BYTES);
    stacked_lstm_kernel<<<Bb / ROWS, NTHREAD, SMEM_BYTES>>>(
        (const float*)d_in[0],
        (const float*)d_in[1], (const float*)d_in[2], (const float*)d_in[3],
        (const float*)d_in[4], (const float*)d_in[5], (const float*)d_in[6],
        (const float*)d_in[7], (const float*)d_in[8], (const float*)d_in[9],
        (const float*)d_in[10], (const float*)d_in[11],
        (float*)d_out);
}